// round 6
// baseline (speedup 1.0000x reference)
#include <cuda_runtime.h>
#include <cuda_bf16.h>
#include <cstdint>
#include <cstddef>

// PCLinearClassifierV2: PC relaxation is algebraically identity (initial
// errors are exactly zero and stay zero), so output = 3-layer MLP forward:
//   h2 = relu(obs) @ W2^T + b2 ; h1 = relu(h2) @ W1^T + b1 ; out = relu(h1) @ W0^T + b0
//
// bf16 split-precision (hi/lo, 3 products) GEMM on mma.sync.m16n8k16.
// fp32 register accumulators. BM=128, BN=64, BK=32, 256 thr, 2-stage
// cp.async pipeline, pitch-80 conflict-free smem, 2 CTAs/SM.

#define S0 1000
#define S1 2048
#define S2 1024
#define S3 4096
#define BATCH 1024

#define BM 128
#define BN 64
#define BK 32
#define NTHR 256

#define PITCHB 80u                      // bytes per smem row (32 bf16 + pad)
#define A_HI 0u
#define A_LO (128u * PITCHB)            // 10240
#define W_HI (2u * 128u * PITCHB)       // 20480
#define W_LO (W_HI + 64u * PITCHB)      // 25600
#define STAGE (W_LO + 64u * PITCHB)     // 30720
#define SMEM_BYTES (2u * STAGE)         // 61440 -> 2 CTAs/SM

// ---------------- scratch (bf16 hi/lo copies + hidden activations) ----------
__device__ __align__(256) __nv_bfloat16 g_obs_hi[BATCH*S3], g_obs_lo[BATCH*S3];
__device__ __align__(256) __nv_bfloat16 g_W2_hi [S2*S3],    g_W2_lo [S2*S3];
__device__ __align__(256) __nv_bfloat16 g_W1_hi [S1*S2],    g_W1_lo [S1*S2];
__device__ __align__(256) __nv_bfloat16 g_W0_hi [S0*S1],    g_W0_lo [S0*S1];
__device__ __align__(256) __nv_bfloat16 g_h2_hi [BATCH*S2], g_h2_lo [BATCH*S2];
__device__ __align__(256) __nv_bfloat16 g_h1_hi [BATCH*S1], g_h1_lo [BATCH*S1];

// ---------------- fp32 -> bf16 hi/lo split, vectorized ----------------------
// Each thread: 2 x float4 (32B) -> uint4 hi (8 bf16) + uint4 lo (8 bf16).
__global__ void split_kernel(const float4* __restrict__ src,
                             uint4* __restrict__ hi, uint4* __restrict__ lo,
                             int n8, int do_relu)
{
    int i = blockIdx.x * blockDim.x + threadIdx.x;
    if (i >= n8) return;
    float4 v0 = src[2*i], v1 = src[2*i+1];
    float a[8] = {v0.x, v0.y, v0.z, v0.w, v1.x, v1.y, v1.z, v1.w};
    if (do_relu) {
#pragma unroll
        for (int e = 0; e < 8; e++) a[e] = fmaxf(a[e], 0.f);
    }
    uint32_t hw[4], lw[4];
#pragma unroll
    for (int p = 0; p < 4; p++) {
        __nv_bfloat16 h0 = __float2bfloat16(a[2*p]);
        __nv_bfloat16 h1 = __float2bfloat16(a[2*p+1]);
        __nv_bfloat16 l0 = __float2bfloat16(a[2*p]   - __bfloat162float(h0));
        __nv_bfloat16 l1 = __float2bfloat16(a[2*p+1] - __bfloat162float(h1));
        __nv_bfloat162 hp = __halves2bfloat162(h0, h1);
        __nv_bfloat162 lp = __halves2bfloat162(l0, l1);
        hw[p] = *(uint32_t*)&hp;
        lw[p] = *(uint32_t*)&lp;
    }
    hi[i] = make_uint4(hw[0], hw[1], hw[2], hw[3]);
    lo[i] = make_uint4(lw[0], lw[1], lw[2], lw[3]);
}

// ---------------- PTX helpers -----------------------------------------------
__device__ __forceinline__ uint32_t smem_u32(const void* p) {
    uint32_t a;
    asm("{ .reg .u64 t; cvta.to.shared.u64 t, %1; cvt.u32.u64 %0, t; }" : "=r"(a) : "l"(p));
    return a;
}

__device__ __forceinline__ void cp16(uint32_t dst, const void* src, bool valid) {
    asm volatile("cp.async.cg.shared.global [%0], [%1], 16, %2;"
                 :: "r"(dst), "l"(src), "r"(valid ? 16u : 0u));
}

__device__ __forceinline__ void ldm_x4(uint32_t* r, uint32_t addr) {
    asm volatile("ldmatrix.sync.aligned.m8n8.x4.shared.b16 {%0,%1,%2,%3}, [%4];"
                 : "=r"(r[0]), "=r"(r[1]), "=r"(r[2]), "=r"(r[3]) : "r"(addr));
}

__device__ __forceinline__ void mma16816(float* c, const uint32_t* a,
                                         uint32_t b0, uint32_t b1) {
    asm volatile(
        "mma.sync.aligned.m16n8k16.row.col.f32.bf16.bf16.f32 "
        "{%0,%1,%2,%3}, {%4,%5,%6,%7}, {%8,%9}, {%0,%1,%2,%3};"
        : "+f"(c[0]), "+f"(c[1]), "+f"(c[2]), "+f"(c[3])
        : "r"(a[0]), "r"(a[1]), "r"(a[2]), "r"(a[3]), "r"(b0), "r"(b1));
}

// ---------------- fused GEMM ------------------------------------------------
// mode 0: out = relu(D + bias) -> bf16 hi/lo ; mode 1: out = D + bias -> fp32
__global__ __launch_bounds__(NTHR, 2)
void gemm_mma(const __nv_bfloat16* __restrict__ Ahi, const __nv_bfloat16* __restrict__ Alo,
              const __nv_bfloat16* __restrict__ Whi, const __nv_bfloat16* __restrict__ Wlo,
              const float* __restrict__ bias,
              float* __restrict__ outF,
              __nv_bfloat16* __restrict__ outHi, __nv_bfloat16* __restrict__ outLo,
              int N, int K, int mode)
{
    extern __shared__ char smem[];
    const uint32_t sbase = smem_u32(smem);
    const int tid  = threadIdx.x;
    const int lane = tid & 31;
    const int wid  = tid >> 5;
    const int wm   = wid >> 1;      // 0..3 (M)
    const int wn   = wid & 1;       // 0..1 (N)
    const int bm   = blockIdx.y * BM;
    const int bn   = blockIdx.x * BN;
    const int T    = K / BK;

    float acc[2][4][4];
#pragma unroll
    for (int mt = 0; mt < 2; mt++)
#pragma unroll
        for (int nt = 0; nt < 4; nt++)
#pragma unroll
            for (int e = 0; e < 4; e++) acc[mt][nt][e] = 0.f;

    // -------- stage loader: 6 cp.async of 16B per thread + commit --------
    // rows are 64B (4 chunks of 16B), pitch 80B.
    auto load_stage = [&](int t) {
        const uint32_t sb = sbase + (uint32_t)(t & 1) * STAGE;
        const size_t k0 = (size_t)t * BK;
#pragma unroll
        for (int i = 0; i < 2; i++) {            // A: 128 rows x 4 chunks
            int idx = tid + i * NTHR;
            int row = idx >> 2, ch = idx & 3;
            uint32_t d = sb + (uint32_t)row * PITCHB + (uint32_t)ch * 16u;
            size_t go = (size_t)(bm + row) * (size_t)K + k0 + (size_t)(ch << 3);
            cp16(d + A_HI, Ahi + go, true);
            cp16(d + A_LO, Alo + go, true);
        }
        {                                        // W: 64 rows x 4 chunks
            int row = tid >> 2, ch = tid & 3;
            bool v = (bn + row) < N;
            int rs = v ? (bn + row) : 0;
            uint32_t d = sb + (uint32_t)row * PITCHB + (uint32_t)ch * 16u;
            size_t go = (size_t)rs * (size_t)K + k0 + (size_t)(ch << 3);
            cp16(d + W_HI, Whi + go, v);
            cp16(d + W_LO, Wlo + go, v);
        }
        asm volatile("cp.async.commit_group;" ::: "memory");
    };

    load_stage(0);
    load_stage(1);

    const int arow = wm * 32 + (lane & 15);
    const int brow = wn * 32 + (lane & 15);
    const int koff = (lane >> 4) << 3;           // 0 or 8

    for (int t = 0; t < T; t++) {
        asm volatile("cp.async.wait_group 1;" ::: "memory");
        __syncthreads();                         // stage t visible to all

        const uint32_t sb = sbase + (uint32_t)(t & 1) * STAGE;
#pragma unroll
        for (int ks = 0; ks < 2; ks++) {
            const uint32_t kb = (uint32_t)(ks * 16 + koff) * 2u;
            uint32_t ah[2][4], al[2][4], bh[2][4], bl[2][4];
#pragma unroll
            for (int mt = 0; mt < 2; mt++) {
                uint32_t ad = sb + (uint32_t)(arow + mt * 16) * PITCHB + kb;
                ldm_x4(ah[mt], ad + A_HI);
                ldm_x4(al[mt], ad + A_LO);
            }
#pragma unroll
            for (int g = 0; g < 2; g++) {
                uint32_t bd = sb + (uint32_t)(brow + g * 16) * PITCHB + kb;
                ldm_x4(bh[g], bd + W_HI);
                ldm_x4(bl[g], bd + W_LO);
            }
#pragma unroll
            for (int mt = 0; mt < 2; mt++)
#pragma unroll
                for (int nt = 0; nt < 4; nt++) {
                    const int g = nt >> 1, s = nt & 1;
                    mma16816(acc[mt][nt], ah[mt], bh[g][s], bh[g][s + 2]);
                    mma16816(acc[mt][nt], ah[mt], bl[g][s], bl[g][s + 2]);
                    mma16816(acc[mt][nt], al[mt], bh[g][s], bh[g][s + 2]);
                }
        }

        __syncthreads();                         // all reads of buf t&1 done
        if (t + 2 < T) load_stage(t + 2);        // overwrite buf t&1
        else asm volatile("cp.async.commit_group;" ::: "memory");
    }

    // -------- epilogue: bias (+relu+split) from registers --------
    const int row0 = bm + wm * 32 + (lane >> 2);
    const int col0 = bn + wn * 32 + (lane & 3) * 2;
#pragma unroll
    for (int mt = 0; mt < 2; mt++) {
#pragma unroll
        for (int nt = 0; nt < 4; nt++) {
            const int c = col0 + nt * 8;
#pragma unroll
            for (int h = 0; h < 2; h++) {
                const int r = row0 + mt * 16 + h * 8;
                float v0 = acc[mt][nt][2 * h + 0];
                float v1 = acc[mt][nt][2 * h + 1];
                if (mode == 0) {
                    v0 = fmaxf(v0 + bias[c], 0.f);
                    v1 = fmaxf(v1 + bias[c + 1], 0.f);
                    __nv_bfloat16 h0 = __float2bfloat16(v0);
                    __nv_bfloat16 h1 = __float2bfloat16(v1);
                    __nv_bfloat16 l0 = __float2bfloat16(v0 - __bfloat162float(h0));
                    __nv_bfloat16 l1 = __float2bfloat16(v1 - __bfloat162float(h1));
                    size_t o = (size_t)r * (size_t)N + (size_t)c;
                    *(__nv_bfloat162*)(outHi + o) = __halves2bfloat162(h0, h1);
                    *(__nv_bfloat162*)(outLo + o) = __halves2bfloat162(l0, l1);
                } else if (c < N) {
                    float2 v = make_float2(v0 + bias[c], v1 + bias[c + 1]);
                    *(float2*)(outF + (size_t)r * (size_t)N + (size_t)c) = v;
                }
            }
        }
    }
}

// ---------------- launch ----------------------------------------------------
extern "C" void kernel_launch(void* const* d_in, const int* in_sizes, int n_in,
                              void* d_out, int out_size)
{
    const float* obs = (const float*)d_in[0];  // (1024, 4096)
    const float* W0  = (const float*)d_in[1];  // (1000, 2048)
    const float* b0  = (const float*)d_in[2];
    const float* W1  = (const float*)d_in[3];  // (2048, 1024)
    const float* b1  = (const float*)d_in[4];
    const float* W2  = (const float*)d_in[5];  // (1024, 4096)
    const float* b2  = (const float*)d_in[6];
    float* out = (float*)d_out;                // (1024, 1000)

    __nv_bfloat16 *obs_hi, *obs_lo, *W2hi, *W2lo, *W1hi, *W1lo, *W0hi, *W0lo;
    __nv_bfloat16 *h2hi, *h2lo, *h1hi, *h1lo;
    cudaGetSymbolAddress((void**)&obs_hi, g_obs_hi);
    cudaGetSymbolAddress((void**)&obs_lo, g_obs_lo);
    cudaGetSymbolAddress((void**)&W2hi,  g_W2_hi);
    cudaGetSymbolAddress((void**)&W2lo,  g_W2_lo);
    cudaGetSymbolAddress((void**)&W1hi,  g_W1_hi);
    cudaGetSymbolAddress((void**)&W1lo,  g_W1_lo);
    cudaGetSymbolAddress((void**)&W0hi,  g_W0_hi);
    cudaGetSymbolAddress((void**)&W0lo,  g_W0_lo);
    cudaGetSymbolAddress((void**)&h2hi,  g_h2_hi);
    cudaGetSymbolAddress((void**)&h2lo,  g_h2_lo);
    cudaGetSymbolAddress((void**)&h1hi,  g_h1_hi);
    cudaGetSymbolAddress((void**)&h1lo,  g_h1_lo);

    cudaFuncSetAttribute(gemm_mma, cudaFuncAttributeMaxDynamicSharedMemorySize, SMEM_BYTES);

    {   // bf16 hi/lo splits (relu fused into obs split); n8 = elems/8
        int n8;
        n8 = BATCH*S3/8; split_kernel<<<(n8+255)/256, 256>>>((const float4*)obs,
             (uint4*)obs_hi, (uint4*)obs_lo, n8, 1);
        n8 = S2*S3/8;    split_kernel<<<(n8+255)/256, 256>>>((const float4*)W2,
             (uint4*)W2hi, (uint4*)W2lo, n8, 0);
        n8 = S1*S2/8;    split_kernel<<<(n8+255)/256, 256>>>((const float4*)W1,
             (uint4*)W1hi, (uint4*)W1lo, n8, 0);
        n8 = S0*S1/8;    split_kernel<<<(n8+255)/256, 256>>>((const float4*)W0,
             (uint4*)W0hi, (uint4*)W0lo, n8, 0);
    }

    dim3 blk(NTHR);
    // h2 = relu(obs) @ W2^T + b2 : N=1024, K=4096 -> 16x8 = 128 CTAs
    gemm_mma<<<dim3(S2/BN, BATCH/BM), blk, SMEM_BYTES>>>(
        obs_hi, obs_lo, W2hi, W2lo, b2, nullptr, h2hi, h2lo, S2, S3, 0);
    // h1 = relu(h2) @ W1^T + b1 : N=2048, K=1024 -> 32x8 = 256 CTAs
    gemm_mma<<<dim3(S1/BN, BATCH/BM), blk, SMEM_BYTES>>>(
        h2hi, h2lo, W1hi, W1lo, b1, nullptr, h1hi, h1lo, S1, S2, 0);
    // out = relu(h1) @ W0^T + b0 : N=1000, K=2048 -> 16x8 = 128 CTAs
    gemm_mma<<<dim3((S0 + BN - 1)/BN, BATCH/BM), blk, SMEM_BYTES>>>(
        h1hi, h1lo, W0hi, W0lo, b0, out, nullptr, nullptr, S0, S1, 1);
}